// round 3
// baseline (speedup 1.0000x reference)
#include <cuda_runtime.h>
#include <cuda_bf16.h>
#include <cstdint>
#include <math.h>

// Problem constants
#define B_  32
#define N_  64
#define D_  30
#define ND_ 64
#define F0_ 64
#define H1_ 128
#define H2_ 64
#define H3_ 32
#define L_  8

// ---------------- device scratch (no allocation allowed) ----------------
__device__ float g_xenc[B_*N_*H3_];       // 32*64*32
__device__ float g_x2[B_*N_];
__device__ float g_denc[D_*ND_*H3_];
__device__ float g_dsamp[D_*ND_*H3_];
__device__ float g_y2[D_*ND_];
__device__ float g_z[H3_+1];              // z[0..31], c0 at [32]
__device__ float g_klpart[D_];
__device__ float g_M[B_*D_*N_*ND_];       // 3.93M floats
__device__ float g_GM[(size_t)L_*B_*D_*N_*ND_]; // 31.5M floats (~126MB)
__device__ float g_gd[L_*B_*D_*32];

__constant__ float c_lamda[8] = {0.01f,0.1f,0.5f,1.0f,3.0f,5.0f,10.0f,20.0f};

// ---------------- JAX threefry2x32 (partitionable path, JAX >= 0.5) ------
__device__ __forceinline__ uint32_t rotl32(uint32_t x, int r){
    return (x << r) | (x >> (32 - r));
}
// u = jax.random.uniform(key(42), (30,64)) element i (row-major), size 1920.
// Partitionable threefry: per-element counter (hi=0, lo=i), bits = out0 ^ out1.
__device__ float jax_uniform_1920(int i){
    uint32_t x0 = 0u;              // hi word of uint64 counter
    uint32_t x1 = (uint32_t)i;     // lo word
    const uint32_t k0 = 0u, k1 = 42u;
    const uint32_t k2 = 0u ^ 42u ^ 0x1BD11BDAu;
    x0 += k0; x1 += k1;
    #define FOUR_ROUNDS(a,b,c,d) \
        x0 += x1; x1 = rotl32(x1,a); x1 ^= x0; \
        x0 += x1; x1 = rotl32(x1,b); x1 ^= x0; \
        x0 += x1; x1 = rotl32(x1,c); x1 ^= x0; \
        x0 += x1; x1 = rotl32(x1,d); x1 ^= x0;
    FOUR_ROUNDS(13,15,26,6);  x0 += k1; x1 += k2 + 1u;
    FOUR_ROUNDS(17,29,16,24); x0 += k2; x1 += k0 + 2u;
    FOUR_ROUNDS(13,15,26,6);  x0 += k0; x1 += k1 + 3u;
    FOUR_ROUNDS(17,29,16,24); x0 += k1; x1 += k2 + 4u;
    FOUR_ROUNDS(13,15,26,6);  x0 += k2; x1 += k0 + 5u;
    #undef FOUR_ROUNDS
    uint32_t bits = x0 ^ x1;
    uint32_t fb = (bits >> 9) | 0x3f800000u;
    return __uint_as_float(fb) - 1.0f;
}

// ---------------- GCN (shared by both branches) --------------------------
// branch 0: x (32 graphs) -> g_xenc, g_x2 ; branch 1: dict (30 graphs) -> g_denc
__global__ void gcn_kernel(const float* __restrict__ xg, const float* __restrict__ adjg,
    const float* __restrict__ W1, const float* __restrict__ b1,
    const float* __restrict__ W2, const float* __restrict__ b2,
    const float* __restrict__ W3, const float* __restrict__ b3,
    int branch)
{
    extern __shared__ float sm[];
    float* adj_s = sm;                 // 4096
    float* t     = sm + 4096;          // 8192
    float* h     = sm + 4096 + 8192;   // 8192
    int g = blockIdx.x;
    const float* x   = xg   + g*64*64;
    const float* adj = adjg + g*64*64;
    int tid = threadIdx.x;

    for (int i = tid; i < 4096; i += blockDim.x) adj_s[i] = adj[i];
    __syncthreads();

    // t1 = x @ W1  (64 x 128)
    for (int i = tid; i < 64*128; i += blockDim.x){
        int n = i >> 7, j = i & 127;
        float acc = 0.f;
        #pragma unroll 8
        for (int f = 0; f < 64; f++) acc += x[n*64+f] * W1[f*128+j];
        t[i] = acc;
    }
    __syncthreads();
    // h1 = relu(adj @ t1 + b1)
    for (int i = tid; i < 64*128; i += blockDim.x){
        int n = i >> 7, j = i & 127;
        float acc = b1[j];
        #pragma unroll 8
        for (int k = 0; k < 64; k++) acc += adj_s[n*64+k] * t[k*128+j];
        h[i] = fmaxf(acc, 0.f);
    }
    __syncthreads();
    // t2 = h1 @ W2  (64 x 64)
    for (int i = tid; i < 64*64; i += blockDim.x){
        int n = i >> 6, j = i & 63;
        float acc = 0.f;
        #pragma unroll 8
        for (int k = 0; k < 128; k++) acc += h[n*128+k] * W2[k*64+j];
        t[i] = acc;
    }
    __syncthreads();
    // h2 = relu(adj @ t2 + b2)   (t2 in t[0,4096), h2 in t[4096,8192))
    for (int i = tid; i < 64*64; i += blockDim.x){
        int n = i >> 6, j = i & 63;
        float acc = b2[j];
        #pragma unroll 8
        for (int k = 0; k < 64; k++) acc += adj_s[n*64+k] * t[k*64+j];
        t[4096 + i] = fmaxf(acc, 0.f);
    }
    __syncthreads();
    // t3 = h2 @ W3  (64 x 32)
    for (int i = tid; i < 64*32; i += blockDim.x){
        int n = i >> 5, j = i & 31;
        float acc = 0.f;
        #pragma unroll 8
        for (int k = 0; k < 64; k++) acc += t[4096 + n*64+k] * W3[k*32+j];
        h[i] = acc;
    }
    __syncthreads();
    // enc = adj @ t3 + b3
    for (int i = tid; i < 64*32; i += blockDim.x){
        int n = i >> 5, j = i & 31;
        float acc = b3[j];
        #pragma unroll 8
        for (int k = 0; k < 64; k++) acc += adj_s[n*64+k] * h[k*32+j];
        t[i] = acc;   // keep for x2
        if (branch == 0) g_xenc[g*2048 + i] = acc;
        else             g_denc[g*2048 + i] = acc;
    }
    __syncthreads();
    if (branch == 0 && tid < 64){
        float s = 0.f;
        #pragma unroll
        for (int f = 0; f < 32; f++){ float v = t[tid*32+f]; s += v*v; }
        g_x2[g*64 + tid] = s;
    }
}

// ---------------- attention coefficient fold: z[f], c0 -------------------
__global__ void zc_kernel(const float* __restrict__ mlp_w, const float* __restrict__ mlp_b,
                          const float* __restrict__ mlp2_w, const float* __restrict__ mlp2_b)
{
    __shared__ float yw[32][32];  // [b][f]
    int tid = threadIdx.x;
    if (tid < 1024){
        int b = tid >> 5, f = tid & 31;
        float ss = 0.f, sw = 0.f;
        #pragma unroll 8
        for (int n = 0; n < 64; n++){
            float v = g_xenc[(b*64+n)*32 + f];
            ss += v*v;
            sw += mlp_w[n]*v;
        }
        yw[b][f] = sw / (sqrtf(ss) + 1e-12f);
    }
    __syncthreads();
    if (tid < 32){
        float acc = 0.f;
        #pragma unroll
        for (int b = 0; b < 32; b++) acc += mlp2_w[b]*yw[b][tid];
        g_z[tid] = acc;
    }
    if (tid == 0){
        float s = 0.f;
        #pragma unroll
        for (int b = 0; b < 32; b++) s += mlp2_w[b];
        g_z[32] = mlp_b[0]*s + mlp2_b[0];
    }
}

// ---------------- attn / bernoulli / d_samp / y2 / kl --------------------
__global__ void attn_kernel(void)
{
    __shared__ float nrm[32];
    __shared__ float klsh[64];
    int d = blockIdx.x, tid = threadIdx.x;
    const float* de = g_denc + d*2048;
    if (tid < 32){
        float s = 0.f;
        #pragma unroll 8
        for (int m = 0; m < 64; m++){ float v = de[m*32+tid]; s += v*v; }
        nrm[tid] = sqrtf(s) + 1e-12f;
    }
    __syncthreads();
    int m = tid;  // 64 threads
    float p = g_z[32];
    #pragma unroll
    for (int f = 0; f < 32; f++) p += (de[m*32+f]/nrm[f]) * g_z[f];
    float attn = 1.f/(1.f + expf(-p));
    float u = jax_uniform_1920(d*64 + m);
    float bern = (u < attn) ? 1.f : 0.f;
    float ss = 0.f;
    #pragma unroll
    for (int f = 0; f < 32; f++){
        float v = de[m*32+f];
        g_dsamp[d*2048 + m*32+f] = bern*v;
        ss += v*v;
    }
    g_y2[d*64+m] = bern*ss;
    klsh[m] = attn*logf(attn*2.f) + (1.f-attn)*logf((1.f-attn)*2.f);
    __syncthreads();
    if (tid == 0){
        float s = 0.f;
        for (int i = 0; i < 64; i++) s += klsh[i];
        g_klpart[d] = s;
    }
}

// ---------------- M[b,d,n,m] = x2 + y2 - 2*xy -----------------------------
__global__ void m_kernel(void)
{
    __shared__ float xs[2048], ds[2048];
    int d = blockIdx.x, b = blockIdx.y, tid = threadIdx.x;
    for (int i = tid; i < 2048; i += 256){
        xs[i] = g_xenc[b*2048+i];
        ds[i] = g_dsamp[d*2048+i];
    }
    __syncthreads();
    float* Mout = g_M + (b*30+d)*4096;
    for (int i = tid; i < 4096; i += 256){
        int n = i >> 6, m = i & 63;
        float acc = 0.f;
        #pragma unroll
        for (int f = 0; f < 32; f++) acc += xs[n*32+f]*ds[m*32+f];
        Mout[i] = g_x2[b*64+n] + g_y2[d*64+m] - 2.f*acc;
    }
}

// ---------------- Sinkhorn per (lb, d), writes GM = Gn * M ----------------
__global__ void sinkhorn_kernel(const int* __restrict__ num_node,
                                const int* __restrict__ dict_nnode)
{
    __shared__ float Km[64*65];
    __shared__ float red[4][64];
    __shared__ float red2[4][64];
    __shared__ float ui[64], vi[64], wis[64], wjs[64];
    __shared__ float rowmax[64], rowmin[64];

    int d = blockIdx.x, lb = blockIdx.y;
    int b = lb & 31, l = lb >> 5;
    float lam = c_lamda[l];
    int tid = threadIdx.x;
    const float* Mp = g_M + (b*30+d)*4096;
    int nn = num_node[b], dn = dict_nnode[d];

    for (int i = tid; i < 4096; i += 256){
        int n = i >> 6, m = i & 63;
        float mask = (n < nn && m < dn) ? 1.f : 0.f;
        Km[n*65+m] = mask * expf(-Mp[i]*lam);
    }
    if (tid < 64){
        ui[tid]  = 1.f;
        wis[tid] = (tid < nn) ? 1.f/(float)nn : 0.f;
        wjs[tid] = (tid < dn) ? 1.f/(float)dn : 0.f;
    }
    __syncthreads();

    int c = tid & 63, q = tid >> 6;
    for (int it = 0; it < 10; it++){
        float p = 0.f;
        #pragma unroll
        for (int n = 0; n < 16; n++) p += Km[(q*16+n)*65 + c] * ui[q*16+n];
        red[q][c] = p;
        __syncthreads();
        if (tid < 64) vi[tid] = wjs[tid] / (red[0][tid]+red[1][tid]+red[2][tid]+red[3][tid] + 1e-6f);
        __syncthreads();
        p = 0.f;
        #pragma unroll
        for (int mm = 0; mm < 16; mm++) p += Km[c*65 + (q*16+mm)] * vi[q*16+mm];
        red[q][c] = p;
        __syncthreads();
        if (tid < 64) ui[tid] = wis[tid] / (red[0][tid]+red[1][tid]+red[2][tid]+red[3][tid] + 1e-6f);
        __syncthreads();
    }

    // G = ui*Km*vi; per-row (over m) min/max; GM = (G-Gmin)/(Gmax-Gmin+eps)*M
    float gmx = -3.4e38f, gmn = 3.4e38f;
    #pragma unroll
    for (int mm = 0; mm < 16; mm++){
        float g = ui[c]*Km[c*65 + (q*16+mm)]*vi[q*16+mm];
        gmx = fmaxf(gmx, g); gmn = fminf(gmn, g);
    }
    red[q][c] = gmx; red2[q][c] = gmn;
    __syncthreads();
    if (tid < 64){
        rowmax[tid] = fmaxf(fmaxf(red[0][tid],red[1][tid]), fmaxf(red[2][tid],red[3][tid]));
        rowmin[tid] = fminf(fminf(red2[0][tid],red2[1][tid]), fminf(red2[2][tid],red2[3][tid]));
    }
    __syncthreads();
    float* out = g_GM + ((size_t)lb*30 + d)*4096;
    for (int i = tid; i < 4096; i += 256){
        int n = i >> 6, m = i & 63;
        float g = ui[n]*Km[n*65+m]*vi[m];
        float gn = (g - rowmin[n]) / (rowmax[n] - rowmin[n] + 1e-6f);
        out[i] = gn * Mp[i];
    }
}

// ---------------- gd = GM(7680x4096) @ dist_para(4096x32) ----------------
__global__ void gd_kernel(const float* __restrict__ dp)
{
    __shared__ float dps[64*32];
    int row0 = blockIdx.x * 8;
    int tid = threadIdx.x;
    int r = tid >> 5, k = tid & 31;
    float acc = 0.f;
    const float* gmr = g_GM + (size_t)(row0 + r)*4096;
    for (int j0 = 0; j0 < 4096; j0 += 64){
        for (int i = tid; i < 64*32; i += 256) dps[i] = dp[(size_t)(j0 + (i>>5))*32 + (i&31)];
        __syncthreads();
        #pragma unroll 8
        for (int j = 0; j < 64; j++) acc += gmr[j0+j] * dps[j*32+k];
        __syncthreads();
    }
    g_gd[(row0+r)*32 + k] = acc;
}

// ---------------- softmax mixture + FC head + KL --------------------------
__global__ void final_kernel(const float* __restrict__ wl,
    const float* __restrict__ fc1w, const float* __restrict__ fc1b,
    const float* __restrict__ fc2w, const float* __restrict__ fc2b,
    float* __restrict__ out, int out_size)
{
    __shared__ float sc[8];
    __shared__ float coeff[8];
    __shared__ float embed[960];
    __shared__ float h[64];
    int b = blockIdx.x, tid = threadIdx.x;
    int w = tid >> 5, lane = tid & 31;

    // scores per l (warp w handles l=w)
    {
        float p = 0.f;
        for (int j = lane; j < 960; j += 32) p += g_gd[(w*32+b)*960 + j] * wl[j];
        #pragma unroll
        for (int o = 16; o; o >>= 1) p += __shfl_xor_sync(0xffffffffu, p, o);
        if (lane == 0) sc[w] = p;
    }
    __syncthreads();
    if (tid == 0){
        float mx = sc[0];
        #pragma unroll
        for (int l = 1; l < 8; l++) mx = fmaxf(mx, sc[l]);
        float s = 0.f;
        #pragma unroll
        for (int l = 0; l < 8; l++){ coeff[l] = expf(sc[l]-mx); s += coeff[l]; }
        #pragma unroll
        for (int l = 0; l < 8; l++) coeff[l] /= s;
    }
    __syncthreads();
    for (int j = tid; j < 960; j += 256){
        float e = 0.f;
        #pragma unroll
        for (int l = 0; l < 8; l++) e += g_gd[(l*32+b)*960 + j] * coeff[l];
        embed[j] = e;
    }
    __syncthreads();
    if (tid < 64){
        float acc = fc1b[tid];
        for (int j = 0; j < 960; j++) acc += embed[j]*fc1w[tid*960+j];
        h[tid] = acc;
    }
    __syncthreads();
    if (tid < 3){
        float acc = fc2b[tid];
        #pragma unroll
        for (int i = 0; i < 64; i++) acc += h[i]*fc2w[tid*64+i];
        out[b*3+tid] = acc;
    }
    if (b == 0 && tid == 32 && out_size > 96){
        float s = 0.f;
        for (int d = 0; d < 30; d++) s += g_klpart[d];
        out[96] = s;
    }
}

// ---------------- launch ---------------------------------------------------
extern "C" void kernel_launch(void* const* d_in, const int* in_sizes, int n_in,
                              void* d_out, int out_size)
{
    const float* x          = (const float*)d_in[0];
    const float* adj        = (const float*)d_in[1];
    const int*   num_node   = (const int*)  d_in[2];
    const float* dict_feat  = (const float*)d_in[3];
    const float* dict_adj   = (const float*)d_in[4];
    const int*   dict_nnode = (const int*)  d_in[5];
    const float* eW1 = (const float*)d_in[6];
    const float* eb1 = (const float*)d_in[7];
    const float* eW2 = (const float*)d_in[8];
    const float* eb2 = (const float*)d_in[9];
    const float* eW3 = (const float*)d_in[10];
    const float* eb3 = (const float*)d_in[11];
    const float* dW1 = (const float*)d_in[12];
    const float* db1 = (const float*)d_in[13];
    const float* dW2 = (const float*)d_in[14];
    const float* db2 = (const float*)d_in[15];
    const float* dW3 = (const float*)d_in[16];
    const float* db3 = (const float*)d_in[17];
    const float* mlp_w  = (const float*)d_in[18];
    const float* mlp_b  = (const float*)d_in[19];
    const float* mlp2_w = (const float*)d_in[20];
    const float* mlp2_b = (const float*)d_in[21];
    const float* dist_para    = (const float*)d_in[22];
    const float* weight_lamda = (const float*)d_in[23];
    const float* fc1_w = (const float*)d_in[24];
    const float* fc1_b = (const float*)d_in[25];
    const float* fc2_w = (const float*)d_in[26];
    const float* fc2_b = (const float*)d_in[27];

    const int gcn_smem = (4096 + 8192 + 8192) * (int)sizeof(float);  // 80 KB
    cudaFuncSetAttribute(gcn_kernel, cudaFuncAttributeMaxDynamicSharedMemorySize, gcn_smem);

    gcn_kernel<<<32, 256, gcn_smem>>>(x, adj, eW1, eb1, eW2, eb2, eW3, eb3, 0);
    gcn_kernel<<<30, 256, gcn_smem>>>(dict_feat, dict_adj, dW1, db1, dW2, db2, dW3, db3, 1);
    zc_kernel<<<1, 1024>>>(mlp_w, mlp_b, mlp2_w, mlp2_b);
    attn_kernel<<<30, 64>>>();
    m_kernel<<<dim3(30, 32), 256>>>();
    sinkhorn_kernel<<<dim3(30, 256), 256>>>(num_node, dict_nnode);
    gd_kernel<<<960, 256>>>(dist_para);
    final_kernel<<<32, 256>>>(weight_lamda, fc1_w, fc1_b, fc2_w, fc2_b,
                              (float*)d_out, out_size);
}

// round 6
// speedup vs baseline: 2.2836x; 2.2836x over previous
#include <cuda_runtime.h>
#include <cuda_bf16.h>
#include <cstdint>
#include <math.h>

// Problem constants
#define B_  32
#define N_  64
#define D_  30
#define ND_ 64
#define F0_ 64
#define H1_ 128
#define H2_ 64
#define H3_ 32
#define L_  8

// ---------------- device scratch (no allocation allowed) ----------------
__device__ float g_xenc[B_*N_*H3_];
__device__ float g_x2[B_*N_];
__device__ float g_denc[D_*ND_*H3_];
__device__ float g_dsamp[D_*ND_*H3_];
__device__ float g_y2[D_*ND_];
__device__ float g_z[H3_+1];
__device__ float g_klpart[D_];
__device__ float g_M[B_*D_*N_*ND_];                 // 15.7 MB
__device__ float g_GM[(size_t)L_*B_*D_*N_*ND_];     // 126 MB
__device__ float g_gd[L_*B_*D_*32];

__constant__ float c_lamda[8] = {0.01f,0.1f,0.5f,1.0f,3.0f,5.0f,10.0f,20.0f};

// ---------------- JAX threefry2x32 (partitionable path) ------------------
__device__ __forceinline__ uint32_t rotl32(uint32_t x, int r){
    return (x << r) | (x >> (32 - r));
}
__device__ float jax_uniform_1920(int i){
    uint32_t x0 = 0u;
    uint32_t x1 = (uint32_t)i;
    const uint32_t k0 = 0u, k1 = 42u;
    const uint32_t k2 = 0u ^ 42u ^ 0x1BD11BDAu;
    x0 += k0; x1 += k1;
    #define FOUR_ROUNDS(a,b,c,d) \
        x0 += x1; x1 = rotl32(x1,a); x1 ^= x0; \
        x0 += x1; x1 = rotl32(x1,b); x1 ^= x0; \
        x0 += x1; x1 = rotl32(x1,c); x1 ^= x0; \
        x0 += x1; x1 = rotl32(x1,d); x1 ^= x0;
    FOUR_ROUNDS(13,15,26,6);  x0 += k1; x1 += k2 + 1u;
    FOUR_ROUNDS(17,29,16,24); x0 += k2; x1 += k0 + 2u;
    FOUR_ROUNDS(13,15,26,6);  x0 += k0; x1 += k1 + 3u;
    FOUR_ROUNDS(17,29,16,24); x0 += k1; x1 += k2 + 4u;
    FOUR_ROUNDS(13,15,26,6);  x0 += k2; x1 += k0 + 5u;
    #undef FOUR_ROUNDS
    uint32_t bits = x0 ^ x1;
    uint32_t fb = (bits >> 9) | 0x3f800000u;
    return __uint_as_float(fb) - 1.0f;
}

// ---------------- GCN, 4-row register tiled --------------------------------
__global__ void gcn_kernel(const float* __restrict__ xg, const float* __restrict__ adjg,
    const float* __restrict__ W1, const float* __restrict__ b1,
    const float* __restrict__ W2, const float* __restrict__ b2,
    const float* __restrict__ W3, const float* __restrict__ b3,
    int branch)
{
    extern __shared__ float sm[];
    float* adj_s = sm;             // 4096
    float* x_s   = sm + 4096;      // 4096
    float* t     = sm + 8192;      // 8192
    float* h     = sm + 16384;     // 8192
    int g = blockIdx.x;
    const float* x   = xg   + g*64*64;
    const float* adj = adjg + g*64*64;
    int tid = threadIdx.x;

    for (int i = tid; i < 4096; i += 256){ adj_s[i] = adj[i]; x_s[i] = x[i]; }
    __syncthreads();

    // t1 = x_s @ W1  (64x64 @ 64x128)
    for (int idx = tid; idx < 16*128; idx += 256){
        int rg = idx >> 7, j = idx & 127;
        const float* xr = x_s + rg*4*64;
        float a0=0.f,a1=0.f,a2=0.f,a3=0.f;
        #pragma unroll 8
        for (int k = 0; k < 64; k++){
            float w = W1[k*128+j];
            a0 += xr[k]*w; a1 += xr[64+k]*w; a2 += xr[128+k]*w; a3 += xr[192+k]*w;
        }
        t[(rg*4+0)*128+j]=a0; t[(rg*4+1)*128+j]=a1; t[(rg*4+2)*128+j]=a2; t[(rg*4+3)*128+j]=a3;
    }
    __syncthreads();
    // h1 = relu(adj @ t1 + b1)
    for (int idx = tid; idx < 16*128; idx += 256){
        int rg = idx >> 7, j = idx & 127;
        const float* ar = adj_s + rg*4*64;
        float bb = b1[j];
        float a0=bb,a1=bb,a2=bb,a3=bb;
        #pragma unroll 8
        for (int k = 0; k < 64; k++){
            float w = t[k*128+j];
            a0 += ar[k]*w; a1 += ar[64+k]*w; a2 += ar[128+k]*w; a3 += ar[192+k]*w;
        }
        h[(rg*4+0)*128+j]=fmaxf(a0,0.f); h[(rg*4+1)*128+j]=fmaxf(a1,0.f);
        h[(rg*4+2)*128+j]=fmaxf(a2,0.f); h[(rg*4+3)*128+j]=fmaxf(a3,0.f);
    }
    __syncthreads();
    // t2 = h1 @ W2  (64x128 @ 128x64) -> t[0,4096)
    for (int idx = tid; idx < 16*64; idx += 256){
        int rg = idx >> 6, j = idx & 63;
        const float* hr = h + rg*4*128;
        float a0=0.f,a1=0.f,a2=0.f,a3=0.f;
        #pragma unroll 8
        for (int k = 0; k < 128; k++){
            float w = W2[k*64+j];
            a0 += hr[k]*w; a1 += hr[128+k]*w; a2 += hr[256+k]*w; a3 += hr[384+k]*w;
        }
        t[(rg*4+0)*64+j]=a0; t[(rg*4+1)*64+j]=a1; t[(rg*4+2)*64+j]=a2; t[(rg*4+3)*64+j]=a3;
    }
    __syncthreads();
    // h2 = relu(adj @ t2 + b2) -> h[0,4096)
    for (int idx = tid; idx < 16*64; idx += 256){
        int rg = idx >> 6, j = idx & 63;
        const float* ar = adj_s + rg*4*64;
        float bb = b2[j];
        float a0=bb,a1=bb,a2=bb,a3=bb;
        #pragma unroll 8
        for (int k = 0; k < 64; k++){
            float w = t[k*64+j];
            a0 += ar[k]*w; a1 += ar[64+k]*w; a2 += ar[128+k]*w; a3 += ar[192+k]*w;
        }
        h[(rg*4+0)*64+j]=fmaxf(a0,0.f); h[(rg*4+1)*64+j]=fmaxf(a1,0.f);
        h[(rg*4+2)*64+j]=fmaxf(a2,0.f); h[(rg*4+3)*64+j]=fmaxf(a3,0.f);
    }
    __syncthreads();
    // t3 = h2 @ W3  (64x64 @ 64x32) -> t[0,2048)
    for (int idx = tid; idx < 16*32; idx += 256){
        int rg = idx >> 5, j = idx & 31;
        const float* hr = h + rg*4*64;
        float a0=0.f,a1=0.f,a2=0.f,a3=0.f;
        #pragma unroll 8
        for (int k = 0; k < 64; k++){
            float w = W3[k*32+j];
            a0 += hr[k]*w; a1 += hr[64+k]*w; a2 += hr[128+k]*w; a3 += hr[192+k]*w;
        }
        t[(rg*4+0)*32+j]=a0; t[(rg*4+1)*32+j]=a1; t[(rg*4+2)*32+j]=a2; t[(rg*4+3)*32+j]=a3;
    }
    __syncthreads();
    // enc = adj @ t3 + b3 -> h[0,2048) + global
    float* outp = (branch == 0) ? (g_xenc + g*2048) : (g_denc + g*2048);
    for (int idx = tid; idx < 16*32; idx += 256){
        int rg = idx >> 5, j = idx & 31;
        const float* ar = adj_s + rg*4*64;
        float bb = b3[j];
        float a0=bb,a1=bb,a2=bb,a3=bb;
        #pragma unroll 8
        for (int k = 0; k < 64; k++){
            float w = t[k*32+j];
            a0 += ar[k]*w; a1 += ar[64+k]*w; a2 += ar[128+k]*w; a3 += ar[192+k]*w;
        }
        h[(rg*4+0)*32+j]=a0; h[(rg*4+1)*32+j]=a1; h[(rg*4+2)*32+j]=a2; h[(rg*4+3)*32+j]=a3;
        outp[(rg*4+0)*32+j]=a0; outp[(rg*4+1)*32+j]=a1; outp[(rg*4+2)*32+j]=a2; outp[(rg*4+3)*32+j]=a3;
    }
    __syncthreads();
    if (branch == 0 && tid < 64){
        float s = 0.f;
        #pragma unroll
        for (int f = 0; f < 32; f++){ float v = h[tid*32+f]; s += v*v; }
        g_x2[g*64 + tid] = s;
    }
}

// ---------------- attention coefficient fold: z[f], c0 -------------------
__global__ void zc_kernel(const float* __restrict__ mlp_w, const float* __restrict__ mlp_b,
                          const float* __restrict__ mlp2_w, const float* __restrict__ mlp2_b)
{
    __shared__ float yw[32][32];  // [b][f]
    int tid = threadIdx.x;
    if (tid < 1024){
        int b = tid >> 5, f = tid & 31;
        float ss = 0.f, sw = 0.f;
        #pragma unroll 8
        for (int n = 0; n < 64; n++){
            float v = g_xenc[(b*64+n)*32 + f];
            ss += v*v;
            sw += mlp_w[n]*v;
        }
        yw[b][f] = sw / (sqrtf(ss) + 1e-12f);
    }
    __syncthreads();
    if (tid < 32){
        float acc = 0.f;
        #pragma unroll
        for (int b = 0; b < 32; b++) acc += mlp2_w[b]*yw[b][tid];
        g_z[tid] = acc;
    }
    if (tid == 0){
        float s = 0.f;
        #pragma unroll
        for (int b = 0; b < 32; b++) s += mlp2_w[b];
        g_z[32] = mlp_b[0]*s + mlp2_b[0];
    }
}

// ---------------- attn / bernoulli / d_samp / y2 / kl --------------------
__global__ void attn_kernel(void)
{
    __shared__ float nrm[32];
    __shared__ float klsh[64];
    int d = blockIdx.x, tid = threadIdx.x;
    const float* de = g_denc + d*2048;
    if (tid < 32){
        float s = 0.f;
        #pragma unroll 8
        for (int m = 0; m < 64; m++){ float v = de[m*32+tid]; s += v*v; }
        nrm[tid] = sqrtf(s) + 1e-12f;
    }
    __syncthreads();
    int m = tid;  // 64 threads
    float p = g_z[32];
    #pragma unroll
    for (int f = 0; f < 32; f++) p += (de[m*32+f]/nrm[f]) * g_z[f];
    float attn = 1.f/(1.f + expf(-p));
    float u = jax_uniform_1920(d*64 + m);
    float bern = (u < attn) ? 1.f : 0.f;
    float ss = 0.f;
    #pragma unroll
    for (int f = 0; f < 32; f++){
        float v = de[m*32+f];
        g_dsamp[d*2048 + m*32+f] = bern*v;
        ss += v*v;
    }
    g_y2[d*64+m] = bern*ss;
    klsh[m] = attn*logf(attn*2.f) + (1.f-attn)*logf((1.f-attn)*2.f);
    __syncthreads();
    if (tid == 0){
        float s = 0.f;
        for (int i = 0; i < 64; i++) s += klsh[i];
        g_klpart[d] = s;
    }
}

// ---------------- M[b,d,n,m] = x2 + y2 - 2*xy -----------------------------
__global__ void m_kernel(void)
{
    __shared__ float xs[2048], ds[2048];
    int d = blockIdx.x, b = blockIdx.y, tid = threadIdx.x;
    for (int i = tid; i < 2048; i += 256){
        xs[i] = g_xenc[b*2048+i];
        ds[i] = g_dsamp[d*2048+i];
    }
    __syncthreads();
    float* Mout = g_M + (b*30+d)*4096;
    for (int i = tid; i < 4096; i += 256){
        int n = i >> 6, m = i & 63;
        float acc = 0.f;
        #pragma unroll
        for (int f = 0; f < 32; f++) acc += xs[n*32+f]*ds[m*32+f];
        Mout[i] = g_x2[b*64+n] + g_y2[d*64+m] - 2.f*acc;
    }
}

// ---------------- Sinkhorn per (lb, d), writes GM = Gn * M ----------------
__global__ void sinkhorn_kernel(const int* __restrict__ num_node,
                                const int* __restrict__ dict_nnode)
{
    __shared__ float Km[64*65];
    __shared__ float red[4][64];
    __shared__ float red2[4][64];
    __shared__ float ui[64], vi[64], wis[64], wjs[64];
    __shared__ float rowmax[64], rowmin[64];

    int d = blockIdx.x, lb = blockIdx.y;
    int b = lb & 31, l = lb >> 5;
    float lam = c_lamda[l];
    int tid = threadIdx.x;
    const float* Mp = g_M + (b*30+d)*4096;
    int nn = num_node[b], dn = dict_nnode[d];

    for (int i = tid; i < 4096; i += 256){
        int n = i >> 6, m = i & 63;
        float mask = (n < nn && m < dn) ? 1.f : 0.f;
        Km[n*65+m] = mask * __expf(-Mp[i]*lam);
    }
    if (tid < 64){
        ui[tid]  = 1.f;
        wis[tid] = (tid < nn) ? 1.f/(float)nn : 0.f;
        wjs[tid] = (tid < dn) ? 1.f/(float)dn : 0.f;
    }
    __syncthreads();

    int c = tid & 63, q = tid >> 6;
    for (int it = 0; it < 10; it++){
        float p = 0.f;
        #pragma unroll
        for (int n = 0; n < 16; n++) p += Km[(q*16+n)*65 + c] * ui[q*16+n];
        red[q][c] = p;
        __syncthreads();
        if (tid < 64) vi[tid] = wjs[tid] / (red[0][tid]+red[1][tid]+red[2][tid]+red[3][tid] + 1e-6f);
        __syncthreads();
        p = 0.f;
        #pragma unroll
        for (int mm = 0; mm < 16; mm++) p += Km[c*65 + (q*16+mm)] * vi[q*16+mm];
        red[q][c] = p;
        __syncthreads();
        if (tid < 64) ui[tid] = wis[tid] / (red[0][tid]+red[1][tid]+red[2][tid]+red[3][tid] + 1e-6f);
        __syncthreads();
    }

    // G = ui*Km*vi; per-row (over m) min/max; GM = (G-Gmin)/(Gmax-Gmin+eps)*M
    float gmx = -3.4e38f, gmn = 3.4e38f;
    #pragma unroll
    for (int mm = 0; mm < 16; mm++){
        float g = ui[c]*Km[c*65 + (q*16+mm)]*vi[q*16+mm];
        gmx = fmaxf(gmx, g); gmn = fminf(gmn, g);
    }
    red[q][c] = gmx; red2[q][c] = gmn;
    __syncthreads();
    if (tid < 64){
        rowmax[tid] = fmaxf(fmaxf(red[0][tid],red[1][tid]), fmaxf(red[2][tid],red[3][tid]));
        rowmin[tid] = fminf(fminf(red2[0][tid],red2[1][tid]), fminf(red2[2][tid],red2[3][tid]));
    }
    __syncthreads();
    float* out = g_GM + ((size_t)lb*30 + d)*4096;
    for (int i = tid; i < 4096; i += 256){
        int n = i >> 6, m = i & 63;
        float g = ui[n]*Km[n*65+m]*vi[m];
        float gn = (g - rowmin[n]) / (rowmax[n] - rowmin[n] + 1e-6f);
        out[i] = gn * Mp[i];
    }
}

// ---------------- gd = GM(7680x4096) @ dist_para(4096x32), tiled ----------
__global__ void gd_kernel(const float* __restrict__ dp)
{
    extern __shared__ float sm[];
    float* gms = sm;             // 64*128 = 8192 floats (32KB)
    float* dps = sm + 8192;      // 128*32 = 4096 floats (16KB)

    int row0 = blockIdx.x * 64;
    int tid = threadIdx.x;
    int col = tid & 31, rg = tid >> 5;   // warp rg handles rows rg*8..rg*8+7

    float acc[8];
    #pragma unroll
    for (int r = 0; r < 8; r++) acc[r] = 0.f;

    const float4* gm4 = (const float4*)(g_GM);
    const float4* dp4 = (const float4*)dp;

    for (int k0 = 0; k0 < 4096; k0 += 128){
        // stage GM tile: 64 rows x 128 cols = 2048 float4
        for (int i = tid; i < 2048; i += 256){
            int r = i >> 5, q = i & 31;
            ((float4*)gms)[r*32 + q] = gm4[(size_t)(row0 + r)*1024 + (k0 >> 2) + q];
        }
        // stage dp tile: rows k0..k0+127, 32 cols = 1024 float4 (contiguous)
        for (int i = tid; i < 1024; i += 256){
            ((float4*)dps)[i] = dp4[(size_t)k0*8 + i];
        }
        __syncthreads();

        const float* gbase = gms + rg*8*128;
        #pragma unroll 4
        for (int kk = 0; kk < 128; kk += 4){
            float d0 = dps[(kk+0)*32 + col];
            float d1 = dps[(kk+1)*32 + col];
            float d2 = dps[(kk+2)*32 + col];
            float d3 = dps[(kk+3)*32 + col];
            #pragma unroll
            for (int r = 0; r < 8; r++){
                float4 gv = *(const float4*)(gbase + r*128 + kk);
                acc[r] += gv.x*d0 + gv.y*d1 + gv.z*d2 + gv.w*d3;
            }
        }
        __syncthreads();
    }
    #pragma unroll
    for (int r = 0; r < 8; r++)
        g_gd[(row0 + rg*8 + r)*32 + col] = acc[r];
}

// ---------------- softmax mixture + FC head + KL --------------------------
__global__ void final_kernel(const float* __restrict__ wl,
    const float* __restrict__ fc1w, const float* __restrict__ fc1b,
    const float* __restrict__ fc2w, const float* __restrict__ fc2b,
    float* __restrict__ out, int out_size)
{
    __shared__ float sc[8];
    __shared__ float coeff[8];
    __shared__ float embed[960];
    __shared__ float h[64];
    int b = blockIdx.x, tid = threadIdx.x;
    int w = tid >> 5, lane = tid & 31;

    {
        float p = 0.f;
        for (int j = lane; j < 960; j += 32) p += g_gd[(w*32+b)*960 + j] * wl[j];
        #pragma unroll
        for (int o = 16; o; o >>= 1) p += __shfl_xor_sync(0xffffffffu, p, o);
        if (lane == 0) sc[w] = p;
    }
    __syncthreads();
    if (tid == 0){
        float mx = sc[0];
        #pragma unroll
        for (int l = 1; l < 8; l++) mx = fmaxf(mx, sc[l]);
        float s = 0.f;
        #pragma unroll
        for (int l = 0; l < 8; l++){ coeff[l] = expf(sc[l]-mx); s += coeff[l]; }
        #pragma unroll
        for (int l = 0; l < 8; l++) coeff[l] /= s;
    }
    __syncthreads();
    for (int j = tid; j < 960; j += 256){
        float e = 0.f;
        #pragma unroll
        for (int l = 0; l < 8; l++) e += g_gd[(l*32+b)*960 + j] * coeff[l];
        embed[j] = e;
    }
    __syncthreads();
    if (tid < 64){
        float acc = fc1b[tid];
        for (int j = 0; j < 960; j++) acc += embed[j]*fc1w[tid*960+j];
        h[tid] = acc;
    }
    __syncthreads();
    if (tid < 3){
        float acc = fc2b[tid];
        #pragma unroll
        for (int i = 0; i < 64; i++) acc += h[i]*fc2w[tid*64+i];
        out[b*3+tid] = acc;
    }
    if (b == 0 && tid == 32 && out_size > 96){
        float s = 0.f;
        for (int d = 0; d < 30; d++) s += g_klpart[d];
        out[96] = s;
    }
}

// ---------------- launch ---------------------------------------------------
extern "C" void kernel_launch(void* const* d_in, const int* in_sizes, int n_in,
                              void* d_out, int out_size)
{
    const float* x          = (const float*)d_in[0];
    const float* adj        = (const float*)d_in[1];
    const int*   num_node   = (const int*)  d_in[2];
    const float* dict_feat  = (const float*)d_in[3];
    const float* dict_adj   = (const float*)d_in[4];
    const int*   dict_nnode = (const int*)  d_in[5];
    const float* eW1 = (const float*)d_in[6];
    const float* eb1 = (const float*)d_in[7];
    const float* eW2 = (const float*)d_in[8];
    const float* eb2 = (const float*)d_in[9];
    const float* eW3 = (const float*)d_in[10];
    const float* eb3 = (const float*)d_in[11];
    const float* dW1 = (const float*)d_in[12];
    const float* db1 = (const float*)d_in[13];
    const float* dW2 = (const float*)d_in[14];
    const float* db2 = (const float*)d_in[15];
    const float* dW3 = (const float*)d_in[16];
    const float* db3 = (const float*)d_in[17];
    const float* mlp_w  = (const float*)d_in[18];
    const float* mlp_b  = (const float*)d_in[19];
    const float* mlp2_w = (const float*)d_in[20];
    const float* mlp2_b = (const float*)d_in[21];
    const float* dist_para    = (const float*)d_in[22];
    const float* weight_lamda = (const float*)d_in[23];
    const float* fc1_w = (const float*)d_in[24];
    const float* fc1_b = (const float*)d_in[25];
    const float* fc2_w = (const float*)d_in[26];
    const float* fc2_b = (const float*)d_in[27];

    const int gcn_smem = (4096 + 4096 + 8192 + 8192) * (int)sizeof(float);  // 96 KB
    const int gd_smem  = (8192 + 4096) * (int)sizeof(float);                // 48 KB
    cudaFuncSetAttribute(gcn_kernel, cudaFuncAttributeMaxDynamicSharedMemorySize, gcn_smem);
    cudaFuncSetAttribute(gd_kernel,  cudaFuncAttributeMaxDynamicSharedMemorySize, gd_smem);

    gcn_kernel<<<32, 256, gcn_smem>>>(x, adj, eW1, eb1, eW2, eb2, eW3, eb3, 0);
    gcn_kernel<<<30, 256, gcn_smem>>>(dict_feat, dict_adj, dW1, db1, dW2, db2, dW3, db3, 1);
    zc_kernel<<<1, 1024>>>(mlp_w, mlp_b, mlp2_w, mlp2_b);
    attn_kernel<<<30, 64>>>();
    m_kernel<<<dim3(30, 32), 256>>>();
    sinkhorn_kernel<<<dim3(30, 256), 256>>>(num_node, dict_nnode);
    gd_kernel<<<120, 256, gd_smem>>>(dist_para);
    final_kernel<<<32, 256>>>(weight_lamda, fc1_w, fc1_b, fc2_w, fc2_b,
                              (float*)d_out, out_size);
}

// round 7
// speedup vs baseline: 2.3015x; 1.0078x over previous
#include <cuda_runtime.h>
#include <cuda_bf16.h>
#include <cstdint>
#include <math.h>

#define B_  32
#define N_  64
#define D_  30
#define ND_ 64
#define H3_ 32
#define L_  8

// ---------------- device scratch ----------------
__device__ float g_xenc[B_*N_*H3_];
__device__ float g_x2[B_*N_];
__device__ float g_denc[D_*ND_*H3_];
__device__ float g_dsamp[D_*ND_*H3_];
__device__ float g_y2[D_*ND_];
__device__ float g_z[H3_+1];
__device__ float g_klpart[D_];
__device__ float g_M[B_*D_*N_*ND_];          // 15.7 MB
__device__ float4 g_vwd[D_*N_*ND_];          // [d][i] -> (s, t0, t1, t2)  2 MB
__device__ float4 g_part[L_*B_*D_];          // per (lb,d) partial (s,t0,t1,t2)

__constant__ float c_lamda[8] = {0.01f,0.1f,0.5f,1.0f,3.0f,5.0f,10.0f,20.0f};

// ---------------- JAX threefry2x32 (partitionable) ------------------
__device__ __forceinline__ uint32_t rotl32(uint32_t x, int r){
    return (x << r) | (x >> (32 - r));
}
__device__ float jax_uniform_1920(int i){
    uint32_t x0 = 0u;
    uint32_t x1 = (uint32_t)i;
    const uint32_t k0 = 0u, k1 = 42u;
    const uint32_t k2 = 0u ^ 42u ^ 0x1BD11BDAu;
    x0 += k0; x1 += k1;
    #define FOUR_ROUNDS(a,b,c,d) \
        x0 += x1; x1 = rotl32(x1,a); x1 ^= x0; \
        x0 += x1; x1 = rotl32(x1,b); x1 ^= x0; \
        x0 += x1; x1 = rotl32(x1,c); x1 ^= x0; \
        x0 += x1; x1 = rotl32(x1,d); x1 ^= x0;
    FOUR_ROUNDS(13,15,26,6);  x0 += k1; x1 += k2 + 1u;
    FOUR_ROUNDS(17,29,16,24); x0 += k2; x1 += k0 + 2u;
    FOUR_ROUNDS(13,15,26,6);  x0 += k0; x1 += k1 + 3u;
    FOUR_ROUNDS(17,29,16,24); x0 += k1; x1 += k2 + 4u;
    FOUR_ROUNDS(13,15,26,6);  x0 += k2; x1 += k0 + 5u;
    #undef FOUR_ROUNDS
    uint32_t bits = x0 ^ x1;
    uint32_t fb = (bits >> 9) | 0x3f800000u;
    return __uint_as_float(fb) - 1.0f;
}

// ---------------- GCN (both branches in one launch) ----------------------
__global__ void gcn_kernel(
    const float* __restrict__ xg0, const float* __restrict__ adjg0,
    const float* __restrict__ eW1, const float* __restrict__ eb1,
    const float* __restrict__ eW2, const float* __restrict__ eb2,
    const float* __restrict__ eW3, const float* __restrict__ eb3,
    const float* __restrict__ xg1, const float* __restrict__ adjg1,
    const float* __restrict__ dW1, const float* __restrict__ db1,
    const float* __restrict__ dW2, const float* __restrict__ db2,
    const float* __restrict__ dW3, const float* __restrict__ db3)
{
    extern __shared__ float sm[];
    float* adj_s = sm;             // 4096
    float* x_s   = sm + 4096;      // 4096
    float* t     = sm + 8192;      // 8192
    float* h     = sm + 16384;     // 8192
    int branch = (blockIdx.x >= 32) ? 1 : 0;
    int g = branch ? (blockIdx.x - 32) : blockIdx.x;
    const float* x   = (branch ? xg1   : xg0)   + g*64*64;
    const float* adj = (branch ? adjg1 : adjg0) + g*64*64;
    const float* W1 = branch ? dW1 : eW1; const float* b1 = branch ? db1 : eb1;
    const float* W2 = branch ? dW2 : eW2; const float* b2 = branch ? db2 : eb2;
    const float* W3 = branch ? dW3 : eW3; const float* b3 = branch ? db3 : eb3;
    int tid = threadIdx.x;

    for (int i = tid; i < 4096; i += 256){ adj_s[i] = adj[i]; x_s[i] = x[i]; }
    __syncthreads();

    // t1 = x_s @ W1
    for (int idx = tid; idx < 16*128; idx += 256){
        int rg = idx >> 7, j = idx & 127;
        const float* xr = x_s + rg*4*64;
        float a0=0.f,a1=0.f,a2=0.f,a3=0.f;
        #pragma unroll 8
        for (int k = 0; k < 64; k++){
            float w = W1[k*128+j];
            a0 += xr[k]*w; a1 += xr[64+k]*w; a2 += xr[128+k]*w; a3 += xr[192+k]*w;
        }
        t[(rg*4+0)*128+j]=a0; t[(rg*4+1)*128+j]=a1; t[(rg*4+2)*128+j]=a2; t[(rg*4+3)*128+j]=a3;
    }
    __syncthreads();
    // h1 = relu(adj @ t1 + b1)
    for (int idx = tid; idx < 16*128; idx += 256){
        int rg = idx >> 7, j = idx & 127;
        const float* ar = adj_s + rg*4*64;
        float bb = b1[j];
        float a0=bb,a1=bb,a2=bb,a3=bb;
        #pragma unroll 8
        for (int k = 0; k < 64; k++){
            float w = t[k*128+j];
            a0 += ar[k]*w; a1 += ar[64+k]*w; a2 += ar[128+k]*w; a3 += ar[192+k]*w;
        }
        h[(rg*4+0)*128+j]=fmaxf(a0,0.f); h[(rg*4+1)*128+j]=fmaxf(a1,0.f);
        h[(rg*4+2)*128+j]=fmaxf(a2,0.f); h[(rg*4+3)*128+j]=fmaxf(a3,0.f);
    }
    __syncthreads();
    // t2 = h1 @ W2
    for (int idx = tid; idx < 16*64; idx += 256){
        int rg = idx >> 6, j = idx & 63;
        const float* hr = h + rg*4*128;
        float a0=0.f,a1=0.f,a2=0.f,a3=0.f;
        #pragma unroll 8
        for (int k = 0; k < 128; k++){
            float w = W2[k*64+j];
            a0 += hr[k]*w; a1 += hr[128+k]*w; a2 += hr[256+k]*w; a3 += hr[384+k]*w;
        }
        t[(rg*4+0)*64+j]=a0; t[(rg*4+1)*64+j]=a1; t[(rg*4+2)*64+j]=a2; t[(rg*4+3)*64+j]=a3;
    }
    __syncthreads();
    // h2 = relu(adj @ t2 + b2)
    for (int idx = tid; idx < 16*64; idx += 256){
        int rg = idx >> 6, j = idx & 63;
        const float* ar = adj_s + rg*4*64;
        float bb = b2[j];
        float a0=bb,a1=bb,a2=bb,a3=bb;
        #pragma unroll 8
        for (int k = 0; k < 64; k++){
            float w = t[k*64+j];
            a0 += ar[k]*w; a1 += ar[64+k]*w; a2 += ar[128+k]*w; a3 += ar[192+k]*w;
        }
        h[(rg*4+0)*64+j]=fmaxf(a0,0.f); h[(rg*4+1)*64+j]=fmaxf(a1,0.f);
        h[(rg*4+2)*64+j]=fmaxf(a2,0.f); h[(rg*4+3)*64+j]=fmaxf(a3,0.f);
    }
    __syncthreads();
    // t3 = h2 @ W3
    for (int idx = tid; idx < 16*32; idx += 256){
        int rg = idx >> 5, j = idx & 31;
        const float* hr = h + rg*4*64;
        float a0=0.f,a1=0.f,a2=0.f,a3=0.f;
        #pragma unroll 8
        for (int k = 0; k < 64; k++){
            float w = W3[k*32+j];
            a0 += hr[k]*w; a1 += hr[64+k]*w; a2 += hr[128+k]*w; a3 += hr[192+k]*w;
        }
        t[(rg*4+0)*32+j]=a0; t[(rg*4+1)*32+j]=a1; t[(rg*4+2)*32+j]=a2; t[(rg*4+3)*32+j]=a3;
    }
    __syncthreads();
    // enc = adj @ t3 + b3
    float* outp = (branch == 0) ? (g_xenc + g*2048) : (g_denc + g*2048);
    for (int idx = tid; idx < 16*32; idx += 256){
        int rg = idx >> 5, j = idx & 31;
        const float* ar = adj_s + rg*4*64;
        float bb = b3[j];
        float a0=bb,a1=bb,a2=bb,a3=bb;
        #pragma unroll 8
        for (int k = 0; k < 64; k++){
            float w = t[k*32+j];
            a0 += ar[k]*w; a1 += ar[64+k]*w; a2 += ar[128+k]*w; a3 += ar[192+k]*w;
        }
        h[(rg*4+0)*32+j]=a0; h[(rg*4+1)*32+j]=a1; h[(rg*4+2)*32+j]=a2; h[(rg*4+3)*32+j]=a3;
        outp[(rg*4+0)*32+j]=a0; outp[(rg*4+1)*32+j]=a1; outp[(rg*4+2)*32+j]=a2; outp[(rg*4+3)*32+j]=a3;
    }
    __syncthreads();
    if (branch == 0 && tid < 64){
        float s = 0.f;
        #pragma unroll
        for (int f = 0; f < 32; f++){ float v = h[tid*32+f]; s += v*v; }
        g_x2[g*64 + tid] = s;
    }
}

// ---------------- w3 = fc2@fc1 fold + vwd precompute ---------------------
// grid 30 (one per d), 256 threads. vwd[d][i] = (dp[i,:]·wl[d*32:], dp[i,:]·w3[c, d*32:])
__global__ void vwd_kernel(const float* __restrict__ dp, const float* __restrict__ wl,
                           const float* __restrict__ fc1w, const float* __restrict__ fc2w)
{
    __shared__ float w3s[3*960];
    __shared__ float wls[960];
    int tid = threadIdx.x;
    int d = blockIdx.x;
    for (int e = tid; e < 960; e += 256) wls[e] = wl[e];
    for (int e = tid; e < 2880; e += 256){
        int c = e / 960, j = e - c*960;
        float acc = 0.f;
        #pragma unroll 8
        for (int r = 0; r < 64; r++) acc += fc2w[c*64+r] * fc1w[r*960+j];
        w3s[e] = acc;
    }
    __syncthreads();
    int base = d*32;
    for (int i = tid; i < 4096; i += 256){
        const float* dr = dp + (size_t)i*32;
        float s=0.f, t0=0.f, t1=0.f, t2=0.f;
        #pragma unroll 8
        for (int k = 0; k < 32; k++){
            float v = dr[k];
            s  += v * wls[base+k];
            t0 += v * w3s[base+k];
            t1 += v * w3s[960+base+k];
            t2 += v * w3s[1920+base+k];
        }
        g_vwd[d*4096 + i] = make_float4(s, t0, t1, t2);
    }
}

// ---------------- attention coefficient fold: z[f], c0 -------------------
__global__ void zc_kernel(const float* __restrict__ mlp_w, const float* __restrict__ mlp_b,
                          const float* __restrict__ mlp2_w, const float* __restrict__ mlp2_b)
{
    __shared__ float yw[32][32];
    int tid = threadIdx.x;
    if (tid < 1024){
        int b = tid >> 5, f = tid & 31;
        float ss = 0.f, sw = 0.f;
        #pragma unroll 8
        for (int n = 0; n < 64; n++){
            float v = g_xenc[(b*64+n)*32 + f];
            ss += v*v;
            sw += mlp_w[n]*v;
        }
        yw[b][f] = sw / (sqrtf(ss) + 1e-12f);
    }
    __syncthreads();
    if (tid < 32){
        float acc = 0.f;
        #pragma unroll
        for (int b = 0; b < 32; b++) acc += mlp2_w[b]*yw[b][tid];
        g_z[tid] = acc;
    }
    if (tid == 0){
        float s = 0.f;
        #pragma unroll
        for (int b = 0; b < 32; b++) s += mlp2_w[b];
        g_z[32] = mlp_b[0]*s + mlp2_b[0];
    }
}

// ---------------- attn / bernoulli / d_samp / y2 / kl --------------------
__global__ void attn_kernel(void)
{
    __shared__ float nrm[32];
    __shared__ float klsh[64];
    int d = blockIdx.x, tid = threadIdx.x;
    const float* de = g_denc + d*2048;
    if (tid < 32){
        float s = 0.f;
        #pragma unroll 8
        for (int m = 0; m < 64; m++){ float v = de[m*32+tid]; s += v*v; }
        nrm[tid] = sqrtf(s) + 1e-12f;
    }
    __syncthreads();
    int m = tid;
    float p = g_z[32];
    #pragma unroll
    for (int f = 0; f < 32; f++) p += (de[m*32+f]/nrm[f]) * g_z[f];
    float attn = 1.f/(1.f + expf(-p));
    float u = jax_uniform_1920(d*64 + m);
    float bern = (u < attn) ? 1.f : 0.f;
    float ss = 0.f;
    #pragma unroll
    for (int f = 0; f < 32; f++){
        float v = de[m*32+f];
        g_dsamp[d*2048 + m*32+f] = bern*v;
        ss += v*v;
    }
    g_y2[d*64+m] = bern*ss;
    klsh[m] = attn*logf(attn*2.f) + (1.f-attn)*logf((1.f-attn)*2.f);
    __syncthreads();
    if (tid == 0){
        float s = 0.f;
        for (int i = 0; i < 64; i++) s += klsh[i];
        g_klpart[d] = s;
    }
}

// ---------------- M[b,d,n,m] = x2 + y2 - 2*xy -----------------------------
__global__ void m_kernel(void)
{
    __shared__ float xs[2048], ds[2048];
    int d = blockIdx.x, b = blockIdx.y, tid = threadIdx.x;
    for (int i = tid; i < 2048; i += 256){
        xs[i] = g_xenc[b*2048+i];
        ds[i] = g_dsamp[d*2048+i];
    }
    __syncthreads();
    float* Mout = g_M + (b*30+d)*4096;
    for (int i = tid; i < 4096; i += 256){
        int n = i >> 6, m = i & 63;
        float acc = 0.f;
        #pragma unroll
        for (int f = 0; f < 32; f++) acc += xs[n*32+f]*ds[m*32+f];
        Mout[i] = g_x2[b*64+n] + g_y2[d*64+m] - 2.f*acc;
    }
}

// ---------------- Sinkhorn + fused projection epilogue --------------------
// Per (lb,d): runs sinkhorn, then reduces GM tile against vwd -> g_part[lb*30+d]
__global__ void sinkhorn_kernel(const int* __restrict__ num_node,
                                const int* __restrict__ dict_nnode)
{
    __shared__ float Km[64*65];
    __shared__ float red[4][64];
    __shared__ float red2[4][64];
    __shared__ float ui[64], vi[64], wis[64], wjs[64];
    __shared__ float rowmax[64], rowmin[64];
    __shared__ float4 wred[8];

    int d = blockIdx.x, lb = blockIdx.y;
    int b = lb & 31, l = lb >> 5;
    float lam = c_lamda[l];
    int tid = threadIdx.x;
    const float* Mp = g_M + (b*30+d)*4096;
    int nn = num_node[b], dn = dict_nnode[d];

    for (int i = tid; i < 4096; i += 256){
        int n = i >> 6, m = i & 63;
        float mask = (n < nn && m < dn) ? 1.f : 0.f;
        Km[n*65+m] = mask * __expf(-Mp[i]*lam);
    }
    if (tid < 64){
        ui[tid]  = 1.f;
        wis[tid] = (tid < nn) ? 1.f/(float)nn : 0.f;
        wjs[tid] = (tid < dn) ? 1.f/(float)dn : 0.f;
    }
    __syncthreads();

    int c = tid & 63, q = tid >> 6;
    for (int it = 0; it < 10; it++){
        float p = 0.f;
        #pragma unroll
        for (int n = 0; n < 16; n++) p += Km[(q*16+n)*65 + c] * ui[q*16+n];
        red[q][c] = p;
        __syncthreads();
        if (tid < 64) vi[tid] = wjs[tid] / (red[0][tid]+red[1][tid]+red[2][tid]+red[3][tid] + 1e-6f);
        __syncthreads();
        p = 0.f;
        #pragma unroll
        for (int mm = 0; mm < 16; mm++) p += Km[c*65 + (q*16+mm)] * vi[q*16+mm];
        red[q][c] = p;
        __syncthreads();
        if (tid < 64) ui[tid] = wis[tid] / (red[0][tid]+red[1][tid]+red[2][tid]+red[3][tid] + 1e-6f);
        __syncthreads();
    }

    // row min/max of G = ui*Km*vi
    float gmx = -3.4e38f, gmn = 3.4e38f;
    #pragma unroll
    for (int mm = 0; mm < 16; mm++){
        float g = ui[c]*Km[c*65 + (q*16+mm)]*vi[q*16+mm];
        gmx = fmaxf(gmx, g); gmn = fminf(gmn, g);
    }
    red[q][c] = gmx; red2[q][c] = gmn;
    __syncthreads();
    if (tid < 64){
        rowmax[tid] = fmaxf(fmaxf(red[0][tid],red[1][tid]), fmaxf(red[2][tid],red[3][tid]));
        rowmin[tid] = fminf(fminf(red2[0][tid],red2[1][tid]), fminf(red2[2][tid],red2[3][tid]));
    }
    __syncthreads();

    // fused epilogue: acc_c = sum_i gn_i * M_i * vwd[d,i].c
    const float4* vw = g_vwd + d*4096;
    float a0=0.f, a1=0.f, a2=0.f, a3=0.f;
    for (int i = tid; i < 4096; i += 256){
        int n = i >> 6, m = i & 63;
        float g = ui[n]*Km[n*65+m]*vi[m];
        float gn = (g - rowmin[n]) / (rowmax[n] - rowmin[n] + 1e-6f);
        float gm = gn * Mp[i];
        float4 v = vw[i];
        a0 += gm*v.x; a1 += gm*v.y; a2 += gm*v.z; a3 += gm*v.w;
    }
    // warp reduce
    #pragma unroll
    for (int o = 16; o; o >>= 1){
        a0 += __shfl_xor_sync(0xffffffffu, a0, o);
        a1 += __shfl_xor_sync(0xffffffffu, a1, o);
        a2 += __shfl_xor_sync(0xffffffffu, a2, o);
        a3 += __shfl_xor_sync(0xffffffffu, a3, o);
    }
    int wid = tid >> 5;
    if ((tid & 31) == 0) wred[wid] = make_float4(a0,a1,a2,a3);
    __syncthreads();
    if (tid == 0){
        float4 s = wred[0];
        #pragma unroll
        for (int w = 1; w < 8; w++){
            float4 t = wred[w];
            s.x += t.x; s.y += t.y; s.z += t.z; s.w += t.w;
        }
        g_part[lb*30 + d] = s;
    }
}

// ---------------- final: softmax over l + folded head + KL ----------------
__global__ void final_kernel(const float* __restrict__ fc1b,
    const float* __restrict__ fc2w, const float* __restrict__ fc2b,
    float* __restrict__ out, int out_size)
{
    __shared__ float4 pl[8];
    int b = blockIdx.x, tid = threadIdx.x;
    int w = tid >> 5, lane = tid & 31;

    // warp w reduces l=w over d
    float4 a = make_float4(0.f,0.f,0.f,0.f);
    if (lane < 30) a = g_part[(w*32+b)*30 + lane];
    #pragma unroll
    for (int o = 16; o; o >>= 1){
        a.x += __shfl_xor_sync(0xffffffffu, a.x, o);
        a.y += __shfl_xor_sync(0xffffffffu, a.y, o);
        a.z += __shfl_xor_sync(0xffffffffu, a.z, o);
        a.w += __shfl_xor_sync(0xffffffffu, a.w, o);
    }
    if (lane == 0) pl[w] = a;
    __syncthreads();
    if (tid == 0){
        float mx = pl[0].x;
        #pragma unroll
        for (int l = 1; l < 8; l++) mx = fmaxf(mx, pl[l].x);
        float s = 0.f;
        float co[8];
        #pragma unroll
        for (int l = 0; l < 8; l++){ co[l] = expf(pl[l].x - mx); s += co[l]; }
        float t0=0.f, t1=0.f, t2=0.f;
        #pragma unroll
        for (int l = 0; l < 8; l++){
            float cf = co[l]/s;
            t0 += cf*pl[l].y; t1 += cf*pl[l].z; t2 += cf*pl[l].w;
        }
        // cc[c] = fc2 @ fc1_b + fc2_b
        float cc0=fc2b[0], cc1=fc2b[1], cc2=fc2b[2];
        for (int r = 0; r < 64; r++){
            float fb = fc1b[r];
            cc0 += fc2w[r]*fb; cc1 += fc2w[64+r]*fb; cc2 += fc2w[128+r]*fb;
        }
        out[b*3+0] = t0 + cc0;
        out[b*3+1] = t1 + cc1;
        out[b*3+2] = t2 + cc2;
    }
    if (b == 0 && tid == 32 && out_size > 96){
        float s = 0.f;
        for (int d = 0; d < 30; d++) s += g_klpart[d];
        out[96] = s;
    }
}

// ---------------- launch ---------------------------------------------------
extern "C" void kernel_launch(void* const* d_in, const int* in_sizes, int n_in,
                              void* d_out, int out_size)
{
    const float* x          = (const float*)d_in[0];
    const float* adj        = (const float*)d_in[1];
    const int*   num_node   = (const int*)  d_in[2];
    const float* dict_feat  = (const float*)d_in[3];
    const float* dict_adj   = (const float*)d_in[4];
    const int*   dict_nnode = (const int*)  d_in[5];
    const float* eW1 = (const float*)d_in[6];
    const float* eb1 = (const float*)d_in[7];
    const float* eW2 = (const float*)d_in[8];
    const float* eb2 = (const float*)d_in[9];
    const float* eW3 = (const float*)d_in[10];
    const float* eb3 = (const float*)d_in[11];
    const float* dW1 = (const float*)d_in[12];
    const float* db1 = (const float*)d_in[13];
    const float* dW2 = (const float*)d_in[14];
    const float* db2 = (const float*)d_in[15];
    const float* dW3 = (const float*)d_in[16];
    const float* db3 = (const float*)d_in[17];
    const float* mlp_w  = (const float*)d_in[18];
    const float* mlp_b  = (const float*)d_in[19];
    const float* mlp2_w = (const float*)d_in[20];
    const float* mlp2_b = (const float*)d_in[21];
    const float* dist_para    = (const float*)d_in[22];
    const float* weight_lamda = (const float*)d_in[23];
    const float* fc1_w = (const float*)d_in[24];
    const float* fc1_b = (const float*)d_in[25];
    const float* fc2_w = (const float*)d_in[26];
    const float* fc2_b = (const float*)d_in[27];

    const int gcn_smem = (4096 + 4096 + 8192 + 8192) * (int)sizeof(float);  // 96 KB
    cudaFuncSetAttribute(gcn_kernel, cudaFuncAttributeMaxDynamicSharedMemorySize, gcn_smem);

    gcn_kernel<<<62, 256, gcn_smem>>>(x, adj, eW1, eb1, eW2, eb2, eW3, eb3,
                                      dict_feat, dict_adj, dW1, db1, dW2, db2, dW3, db3);
    vwd_kernel<<<30, 256>>>(dist_para, weight_lamda, fc1_w, fc2_w);
    zc_kernel<<<1, 1024>>>(mlp_w, mlp_b, mlp2_w, mlp2_b);
    attn_kernel<<<30, 64>>>();
    m_kernel<<<dim3(30, 32), 256>>>();
    sinkhorn_kernel<<<dim3(30, 256), 256>>>(num_node, dict_nnode);
    final_kernel<<<32, 256>>>(fc1_b, fc2_w, fc2_b, (float*)d_out, out_size);
}

// round 9
// speedup vs baseline: 2.8536x; 1.2399x over previous
#include <cuda_runtime.h>
#include <cuda_bf16.h>
#include <cstdint>
#include <math.h>

#define B_  32
#define N_  64
#define D_  30
#define ND_ 64
#define H3_ 32
#define L_  8

// ---------------- device scratch ----------------
__device__ float g_xenc[B_*N_*H3_];
__device__ float g_x2[B_*N_];
__device__ float g_denc[D_*ND_*H3_];
__device__ float g_dsamp[D_*ND_*H3_];
__device__ float g_y2[D_*ND_];
__device__ float g_klpart[D_];
__device__ float4 g_vwd[D_*N_*ND_];          // [d][i] -> (s, t0, t1, t2)  2 MB
__device__ float4 g_part[L_*B_*D_];          // per (l,b,d) partial (s,t0,t1,t2)

__constant__ float c_lamda[8] = {0.01f,0.1f,0.5f,1.0f,3.0f,5.0f,10.0f,20.0f};

// ---------------- JAX threefry2x32 (partitionable) ------------------
__device__ __forceinline__ uint32_t rotl32(uint32_t x, int r){
    return (x << r) | (x >> (32 - r));
}
__device__ float jax_uniform_1920(int i){
    uint32_t x0 = 0u;
    uint32_t x1 = (uint32_t)i;
    const uint32_t k0 = 0u, k1 = 42u;
    const uint32_t k2 = 0u ^ 42u ^ 0x1BD11BDAu;
    x0 += k0; x1 += k1;
    #define FOUR_ROUNDS(a,b,c,d) \
        x0 += x1; x1 = rotl32(x1,a); x1 ^= x0; \
        x0 += x1; x1 = rotl32(x1,b); x1 ^= x0; \
        x0 += x1; x1 = rotl32(x1,c); x1 ^= x0; \
        x0 += x1; x1 = rotl32(x1,d); x1 ^= x0;
    FOUR_ROUNDS(13,15,26,6);  x0 += k1; x1 += k2 + 1u;
    FOUR_ROUNDS(17,29,16,24); x0 += k2; x1 += k0 + 2u;
    FOUR_ROUNDS(13,15,26,6);  x0 += k0; x1 += k1 + 3u;
    FOUR_ROUNDS(17,29,16,24); x0 += k1; x1 += k2 + 4u;
    FOUR_ROUNDS(13,15,26,6);  x0 += k2; x1 += k0 + 5u;
    #undef FOUR_ROUNDS
    uint32_t bits = x0 ^ x1;
    uint32_t fb = (bits >> 9) | 0x3f800000u;
    return __uint_as_float(fb) - 1.0f;
}

// ---------------- GCN (both branches in one launch) ----------------------
__global__ void gcn_kernel(
    const float* __restrict__ xg0, const float* __restrict__ adjg0,
    const float* __restrict__ eW1, const float* __restrict__ eb1,
    const float* __restrict__ eW2, const float* __restrict__ eb2,
    const float* __restrict__ eW3, const float* __restrict__ eb3,
    const float* __restrict__ xg1, const float* __restrict__ adjg1,
    const float* __restrict__ dW1, const float* __restrict__ db1,
    const float* __restrict__ dW2, const float* __restrict__ db2,
    const float* __restrict__ dW3, const float* __restrict__ db3)
{
    extern __shared__ float sm[];
    float* adj_s = sm;             // 4096
    float* x_s   = sm + 4096;      // 4096
    float* t     = sm + 8192;      // 8192
    float* h     = sm + 16384;     // 8192
    int branch = (blockIdx.x >= 32) ? 1 : 0;
    int g = branch ? (blockIdx.x - 32) : blockIdx.x;
    const float* x   = (branch ? xg1   : xg0)   + g*64*64;
    const float* adj = (branch ? adjg1 : adjg0) + g*64*64;
    const float* W1 = branch ? dW1 : eW1; const float* b1 = branch ? db1 : eb1;
    const float* W2 = branch ? dW2 : eW2; const float* b2 = branch ? db2 : eb2;
    const float* W3 = branch ? dW3 : eW3; const float* b3 = branch ? db3 : eb3;
    int tid = threadIdx.x;

    for (int i = tid; i < 4096; i += 256){ adj_s[i] = adj[i]; x_s[i] = x[i]; }
    __syncthreads();

    // t1 = x_s @ W1
    for (int idx = tid; idx < 16*128; idx += 256){
        int rg = idx >> 7, j = idx & 127;
        const float* xr = x_s + rg*4*64;
        float a0=0.f,a1=0.f,a2=0.f,a3=0.f;
        #pragma unroll 8
        for (int k = 0; k < 64; k++){
            float w = W1[k*128+j];
            a0 += xr[k]*w; a1 += xr[64+k]*w; a2 += xr[128+k]*w; a3 += xr[192+k]*w;
        }
        t[(rg*4+0)*128+j]=a0; t[(rg*4+1)*128+j]=a1; t[(rg*4+2)*128+j]=a2; t[(rg*4+3)*128+j]=a3;
    }
    __syncthreads();
    // h1 = relu(adj @ t1 + b1)
    for (int idx = tid; idx < 16*128; idx += 256){
        int rg = idx >> 7, j = idx & 127;
        const float* ar = adj_s + rg*4*64;
        float bb = b1[j];
        float a0=bb,a1=bb,a2=bb,a3=bb;
        #pragma unroll 8
        for (int k = 0; k < 64; k++){
            float w = t[k*128+j];
            a0 += ar[k]*w; a1 += ar[64+k]*w; a2 += ar[128+k]*w; a3 += ar[192+k]*w;
        }
        h[(rg*4+0)*128+j]=fmaxf(a0,0.f); h[(rg*4+1)*128+j]=fmaxf(a1,0.f);
        h[(rg*4+2)*128+j]=fmaxf(a2,0.f); h[(rg*4+3)*128+j]=fmaxf(a3,0.f);
    }
    __syncthreads();
    // t2 = h1 @ W2
    for (int idx = tid; idx < 16*64; idx += 256){
        int rg = idx >> 6, j = idx & 63;
        const float* hr = h + rg*4*128;
        float a0=0.f,a1=0.f,a2=0.f,a3=0.f;
        #pragma unroll 8
        for (int k = 0; k < 128; k++){
            float w = W2[k*64+j];
            a0 += hr[k]*w; a1 += hr[128+k]*w; a2 += hr[256+k]*w; a3 += hr[384+k]*w;
        }
        t[(rg*4+0)*64+j]=a0; t[(rg*4+1)*64+j]=a1; t[(rg*4+2)*64+j]=a2; t[(rg*4+3)*64+j]=a3;
    }
    __syncthreads();
    // h2 = relu(adj @ t2 + b2)
    for (int idx = tid; idx < 16*64; idx += 256){
        int rg = idx >> 6, j = idx & 63;
        const float* ar = adj_s + rg*4*64;
        float bb = b2[j];
        float a0=bb,a1=bb,a2=bb,a3=bb;
        #pragma unroll 8
        for (int k = 0; k < 64; k++){
            float w = t[k*64+j];
            a0 += ar[k]*w; a1 += ar[64+k]*w; a2 += ar[128+k]*w; a3 += ar[192+k]*w;
        }
        h[(rg*4+0)*64+j]=fmaxf(a0,0.f); h[(rg*4+1)*64+j]=fmaxf(a1,0.f);
        h[(rg*4+2)*64+j]=fmaxf(a2,0.f); h[(rg*4+3)*64+j]=fmaxf(a3,0.f);
    }
    __syncthreads();
    // t3 = h2 @ W3
    for (int idx = tid; idx < 16*32; idx += 256){
        int rg = idx >> 5, j = idx & 31;
        const float* hr = h + rg*4*64;
        float a0=0.f,a1=0.f,a2=0.f,a3=0.f;
        #pragma unroll 8
        for (int k = 0; k < 64; k++){
            float w = W3[k*32+j];
            a0 += hr[k]*w; a1 += hr[64+k]*w; a2 += hr[128+k]*w; a3 += hr[192+k]*w;
        }
        t[(rg*4+0)*32+j]=a0; t[(rg*4+1)*32+j]=a1; t[(rg*4+2)*32+j]=a2; t[(rg*4+3)*32+j]=a3;
    }
    __syncthreads();
    // enc = adj @ t3 + b3
    float* outp = (branch == 0) ? (g_xenc + g*2048) : (g_denc + g*2048);
    for (int idx = tid; idx < 16*32; idx += 256){
        int rg = idx >> 5, j = idx & 31;
        const float* ar = adj_s + rg*4*64;
        float bb = b3[j];
        float a0=bb,a1=bb,a2=bb,a3=bb;
        #pragma unroll 8
        for (int k = 0; k < 64; k++){
            float w = t[k*32+j];
            a0 += ar[k]*w; a1 += ar[64+k]*w; a2 += ar[128+k]*w; a3 += ar[192+k]*w;
        }
        h[(rg*4+0)*32+j]=a0; h[(rg*4+1)*32+j]=a1; h[(rg*4+2)*32+j]=a2; h[(rg*4+3)*32+j]=a3;
        outp[(rg*4+0)*32+j]=a0; outp[(rg*4+1)*32+j]=a1; outp[(rg*4+2)*32+j]=a2; outp[(rg*4+3)*32+j]=a3;
    }
    __syncthreads();
    if (branch == 0 && tid < 64){
        float s = 0.f;
        #pragma unroll
        for (int f = 0; f < 32; f++){ float v = h[tid*32+f]; s += v*v; }
        g_x2[g*64 + tid] = s;
    }
}

// ---------------- w3 = fc2@fc1 fold + vwd precompute ---------------------
__global__ void vwd_kernel(const float* __restrict__ dp, const float* __restrict__ wl,
                           const float* __restrict__ fc1w, const float* __restrict__ fc2w)
{
    __shared__ float w3s[3*960];
    __shared__ float wls[960];
    int tid = threadIdx.x;
    int d = blockIdx.x;
    for (int e = tid; e < 960; e += 256) wls[e] = wl[e];
    for (int e = tid; e < 2880; e += 256){
        int c = e / 960, j = e - c*960;
        float acc = 0.f;
        #pragma unroll 8
        for (int r = 0; r < 64; r++) acc += fc2w[c*64+r] * fc1w[r*960+j];
        w3s[e] = acc;
    }
    __syncthreads();
    int base = d*32;
    for (int i = tid; i < 4096; i += 256){
        const float* dr = dp + (size_t)i*32;
        float s=0.f, t0=0.f, t1=0.f, t2=0.f;
        #pragma unroll 8
        for (int k = 0; k < 32; k++){
            float v = dr[k];
            s  += v * wls[base+k];
            t0 += v * w3s[base+k];
            t1 += v * w3s[960+base+k];
            t2 += v * w3s[1920+base+k];
        }
        g_vwd[d*4096 + i] = make_float4(s, t0, t1, t2);
    }
}

// ---------------- attn (with zc folded in) --------------------------------
// grid 30, 256 threads; each block redundantly computes z, then attn for its d
__global__ void attnz_kernel(const float* __restrict__ mlp_w, const float* __restrict__ mlp_b,
                             const float* __restrict__ mlp2_w, const float* __restrict__ mlp2_b)
{
    __shared__ float yw[32][32];
    __shared__ float z[33];
    __shared__ float nrm[32];
    __shared__ float klsh[64];
    int d = blockIdx.x, tid = threadIdx.x;

    // yw[b][f]
    for (int e = tid; e < 1024; e += 256){
        int b = e >> 5, f = e & 31;
        float ss = 0.f, sw = 0.f;
        #pragma unroll 8
        for (int n = 0; n < 64; n++){
            float v = g_xenc[(b*64+n)*32 + f];
            ss += v*v;
            sw += mlp_w[n]*v;
        }
        yw[b][f] = sw / (sqrtf(ss) + 1e-12f);
    }
    __syncthreads();
    if (tid < 32){
        float acc = 0.f;
        #pragma unroll
        for (int b = 0; b < 32; b++) acc += mlp2_w[b]*yw[b][tid];
        z[tid] = acc;
    }
    if (tid == 0){
        float s = 0.f;
        #pragma unroll
        for (int b = 0; b < 32; b++) s += mlp2_w[b];
        z[32] = mlp_b[0]*s + mlp2_b[0];
    }
    const float* de = g_denc + d*2048;
    if (tid >= 64 && tid < 96){
        int f = tid - 64;
        float s = 0.f;
        #pragma unroll 8
        for (int m = 0; m < 64; m++){ float v = de[m*32+f]; s += v*v; }
        nrm[f] = sqrtf(s) + 1e-12f;
    }
    __syncthreads();
    if (tid < 64){
        int m = tid;
        float p = z[32];
        #pragma unroll
        for (int f = 0; f < 32; f++) p += (de[m*32+f]/nrm[f]) * z[f];
        float attn = 1.f/(1.f + expf(-p));
        float u = jax_uniform_1920(d*64 + m);
        float bern = (u < attn) ? 1.f : 0.f;
        float ss = 0.f;
        #pragma unroll
        for (int f = 0; f < 32; f++){
            float v = de[m*32+f];
            g_dsamp[d*2048 + m*32+f] = bern*v;
            ss += v*v;
        }
        g_y2[d*64+m] = bern*ss;
        klsh[m] = attn*logf(attn*2.f) + (1.f-attn)*logf((1.f-attn)*2.f);
    }
    __syncthreads();
    if (tid == 0){
        float s = 0.f;
        for (int i = 0; i < 64; i++) s += klsh[i];
        g_klpart[d] = s;
    }
}

// ---------------- Sinkhorn: per (d,b), ALL 8 lambdas; M built in smem -----
// grid (30,32), 256 threads. Km held in registers (regA: column slice,
// regB: row slice). Fused projection epilogue -> g_part.
__global__ void __launch_bounds__(256, 4)
sinkhorn_kernel(const int* __restrict__ num_node, const int* __restrict__ dict_nnode)
{
    __shared__ float Ms[64*65];      // padded M tile
    __shared__ float xs[2048];
    __shared__ float ds[2048];
    __shared__ float red[4][64];
    __shared__ float red2[4][64];
    __shared__ float ui[64], vi[64], wis[64], wjs[64];
    __shared__ float rowmax[64], rowmin[64];
    __shared__ float4 wred[8];

    int d = blockIdx.x, b = blockIdx.y;
    int tid = threadIdx.x;
    int nn = num_node[b], dn = dict_nnode[d];

    for (int i = tid; i < 2048; i += 256){
        xs[i] = g_xenc[b*2048+i];
        ds[i] = g_dsamp[d*2048+i];
    }
    if (tid < 64){
        wis[tid] = (tid < nn) ? 1.f/(float)nn : 0.f;
        wjs[tid] = (tid < dn) ? 1.f/(float)dn : 0.f;
    }
    __syncthreads();

    // build M tile in smem (padded stride 65)
    for (int i = tid; i < 4096; i += 256){
        int n = i >> 6, m = i & 63;
        float acc = 0.f;
        #pragma unroll
        for (int f = 0; f < 32; f++) acc += xs[n*32+f]*ds[m*32+f];
        Ms[n*65+m] = g_x2[b*64+n] + g_y2[d*64+m] - 2.f*acc;
    }
    __syncthreads();

    int c = tid & 63, q = tid >> 6;
    bool rowInA[16];   // (q*16+n) < nn for regA rows
    const float4* vw = g_vwd + d*4096;

    for (int l = 0; l < 8; l++){
        float lam = c_lamda[l];
        float regA[16], regB[16];
        // regA[n] = Km[q*16+n][c], regB[mm] = Km[c][q*16+mm]
        #pragma unroll
        for (int n = 0; n < 16; n++){
            int row = q*16 + n;
            float mv = Ms[row*65 + c];
            regA[n] = (row < nn && c < dn) ? __expf(-mv*lam) : 0.f;
        }
        #pragma unroll
        for (int mm = 0; mm < 16; mm++){
            int col = q*16 + mm;
            float mv = Ms[c*65 + col];
            regB[mm] = (c < nn && col < dn) ? __expf(-mv*lam) : 0.f;
        }
        if (tid < 64) ui[tid] = 1.f;
        __syncthreads();

        for (int it = 0; it < 10; it++){
            float p = 0.f;
            #pragma unroll
            for (int n = 0; n < 16; n++) p += regA[n] * ui[q*16+n];
            red[q][c] = p;
            __syncthreads();
            if (tid < 64) vi[tid] = wjs[tid] / (red[0][tid]+red[1][tid]+red[2][tid]+red[3][tid] + 1e-6f);
            __syncthreads();
            p = 0.f;
            #pragma unroll
            for (int mm = 0; mm < 16; mm++) p += regB[mm] * vi[q*16+mm];
            red[q][c] = p;
            __syncthreads();
            if (tid < 64) ui[tid] = wis[tid] / (red[0][tid]+red[1][tid]+red[2][tid]+red[3][tid] + 1e-6f);
            __syncthreads();
        }

        // row min/max of G = ui*Km*vi  (row = c, cols q*16+mm)
        float uic = ui[c];
        float gmx = -3.4e38f, gmn = 3.4e38f;
        #pragma unroll
        for (int mm = 0; mm < 16; mm++){
            float g = uic * regB[mm] * vi[q*16+mm];
            gmx = fmaxf(gmx, g); gmn = fminf(gmn, g);
        }
        red[q][c] = gmx; red2[q][c] = gmn;
        __syncthreads();
        if (tid < 64){
            rowmax[tid] = fmaxf(fmaxf(red[0][tid],red[1][tid]), fmaxf(red[2][tid],red[3][tid]));
            rowmin[tid] = fminf(fminf(red2[0][tid],red2[1][tid]), fminf(red2[2][tid],red2[3][tid]));
        }
        __syncthreads();

        // fused epilogue: acc_c = sum gn * M * vwd
        float rmin = rowmin[c];
        float rinv = 1.f / (rowmax[c] - rmin + 1e-6f);
        float a0=0.f, a1=0.f, a2=0.f, a3=0.f;
        #pragma unroll
        for (int mm = 0; mm < 16; mm++){
            int col = q*16 + mm;
            float g  = uic * regB[mm] * vi[col];
            float gn = (g - rmin) * rinv;
            float gm = gn * Ms[c*65 + col];
            float4 v = vw[c*64 + col];
            a0 += gm*v.x; a1 += gm*v.y; a2 += gm*v.z; a3 += gm*v.w;
        }
        #pragma unroll
        for (int o = 16; o; o >>= 1){
            a0 += __shfl_xor_sync(0xffffffffu, a0, o);
            a1 += __shfl_xor_sync(0xffffffffu, a1, o);
            a2 += __shfl_xor_sync(0xffffffffu, a2, o);
            a3 += __shfl_xor_sync(0xffffffffu, a3, o);
        }
        int wid = tid >> 5;
        if ((tid & 31) == 0) wred[wid] = make_float4(a0,a1,a2,a3);
        __syncthreads();
        if (tid == 0){
            float4 s = wred[0];
            #pragma unroll
            for (int w = 1; w < 8; w++){
                float4 t = wred[w];
                s.x += t.x; s.y += t.y; s.z += t.z; s.w += t.w;
            }
            g_part[(l*32+b)*30 + d] = s;
        }
        __syncthreads();
    }
    (void)rowInA;
}

// ---------------- final: softmax over l + folded head + KL ----------------
__global__ void final_kernel(const float* __restrict__ fc1b,
    const float* __restrict__ fc2w, const float* __restrict__ fc2b,
    float* __restrict__ out, int out_size)
{
    __shared__ float4 pl[8];
    int b = blockIdx.x, tid = threadIdx.x;
    int w = tid >> 5, lane = tid & 31;

    float4 a = make_float4(0.f,0.f,0.f,0.f);
    if (lane < 30) a = g_part[(w*32+b)*30 + lane];
    #pragma unroll
    for (int o = 16; o; o >>= 1){
        a.x += __shfl_xor_sync(0xffffffffu, a.x, o);
        a.y += __shfl_xor_sync(0xffffffffu, a.y, o);
        a.z += __shfl_xor_sync(0xffffffffu, a.z, o);
        a.w += __shfl_xor_sync(0xffffffffu, a.w, o);
    }
    if (lane == 0) pl[w] = a;
    __syncthreads();
    if (tid == 0){
        float mx = pl[0].x;
        #pragma unroll
        for (int l = 1; l < 8; l++) mx = fmaxf(mx, pl[l].x);
        float s = 0.f;
        float co[8];
        #pragma unroll
        for (int l = 0; l < 8; l++){ co[l] = expf(pl[l].x - mx); s += co[l]; }
        float t0=0.f, t1=0.f, t2=0.f;
        #pragma unroll
        for (int l = 0; l < 8; l++){
            float cf = co[l]/s;
            t0 += cf*pl[l].y; t1 += cf*pl[l].z; t2 += cf*pl[l].w;
        }
        float cc0=fc2b[0], cc1=fc2b[1], cc2=fc2b[2];
        for (int r = 0; r < 64; r++){
            float fb = fc1b[r];
            cc0 += fc2w[r]*fb; cc1 += fc2w[64+r]*fb; cc2 += fc2w[128+r]*fb;
        }
        out[b*3+0] = t0 + cc0;
        out[b*3+1] = t1 + cc1;
        out[b*3+2] = t2 + cc2;
    }
    if (b == 0 && tid == 32 && out_size > 96){
        float s = 0.f;
        for (int d = 0; d < 30; d++) s += g_klpart[d];
        out[96] = s;
    }
}

// ---------------- launch ---------------------------------------------------
extern "C" void kernel_launch(void* const* d_in, const int* in_sizes, int n_in,
                              void* d_out, int out_size)
{
    const float* x          = (const float*)d_in[0];
    const float* adj        = (const float*)d_in[1];
    const int*   num_node   = (const int*)  d_in[2];
    const float* dict_feat  = (const float*)d_in[3];
    const float* dict_adj   = (const float*)d_in[4];
    const int*   dict_nnode = (const int*)  d_in[5];
    const float* eW1 = (const float*)d_in[6];
    const float* eb1 = (const float*)d_in[7];
    const float* eW2 = (const float*)d_in[8];
    const float* eb2 = (const float*)d_in[9];
    const float* eW3 = (const float*)d_in[10];
    const float* eb3 = (const float*)d_in[11];
    const float* dW1 = (const float*)d_in[12];
    const float* db1 = (const float*)d_in[13];
    const float* dW2 = (const float*)d_in[14];
    const float* db2 = (const float*)d_in[15];
    const float* dW3 = (const float*)d_in[16];
    const float* db3 = (const float*)d_in[17];
    const float* mlp_w  = (const float*)d_in[18];
    const float* mlp_b  = (const float*)d_in[19];
    const float* mlp2_w = (const float*)d_in[20];
    const float* mlp2_b = (const float*)d_in[21];
    const float* dist_para    = (const float*)d_in[22];
    const float* weight_lamda = (const float*)d_in[23];
    const float* fc1_w = (const float*)d_in[24];
    const float* fc1_b = (const float*)d_in[25];
    const float* fc2_w = (const float*)d_in[26];
    const float* fc2_b = (const float*)d_in[27];

    const int gcn_smem = (4096 + 4096 + 8192 + 8192) * (int)sizeof(float);  // 96 KB
    cudaFuncSetAttribute(gcn_kernel, cudaFuncAttributeMaxDynamicSharedMemorySize, gcn_smem);

    gcn_kernel<<<62, 256, gcn_smem>>>(x, adj, eW1, eb1, eW2, eb2, eW3, eb3,
                                      dict_feat, dict_adj, dW1, db1, dW2, db2, dW3, db3);
    vwd_kernel<<<30, 256>>>(dist_para, weight_lamda, fc1_w, fc2_w);
    attnz_kernel<<<30, 256>>>(mlp_w, mlp_b, mlp2_w, mlp2_b);
    sinkhorn_kernel<<<dim3(30, 32), 256>>>(num_node, dict_nnode);
    final_kernel<<<32, 256>>>(fc1_b, fc2_w, fc2_b, (float*)d_out, out_size);
}